// round 1
// baseline (speedup 1.0000x reference)
#include <cuda_runtime.h>
#include <math.h>

#define BB 4
#define TT 8192
#define DD 512
#define HH 512
#define M_TOTAL (BB*TT)        // 32768
#define NC 32                  // scan chunks
#define CL (TT/NC)             // 256 steps per chunk
#define NCH (BB*HH)            // 2048 channels

// Scratch (device globals: allocation-free per harness rules)
__device__ float g_f[(size_t)M_TOTAL*HH];   // forget gate, 64MB
__device__ float g_v[(size_t)M_TOTAL*HH];   // i*g value,   64MB
__device__ float g_cF[NCH*NC];
__device__ float g_cV[NCH*NC];
__device__ float g_hin[NCH*NC];

__device__ __forceinline__ float sp(float z) {
    // softplus, stable for the |z| <= ~30 range seen here
    return (z > 20.f) ? z : log1pf(expf(z));
}

// ---------------------------------------------------------------------------
// Kernel 1: fused 3-way GEMM + gate nonlinearity.
// Computes f_pre/i_pre/h_pre = x@W_{f,i,h}+b, then writes
//   g_f = sigmoid(-diff),  g_v = sigmoid(diff) * g(h_pre)
// where diff = softplus(-f_pre) - softplus(-i_pre),
//       g(x) = x>=0 ? x+0.5 : sigmoid(x).
// ---------------------------------------------------------------------------
#define BM 64
#define BN 64
#define BK 16

__global__ __launch_bounds__(256, 2)
void gemm_gate_kernel(const float* __restrict__ x,
                      const float* __restrict__ Wf, const float* __restrict__ bf,
                      const float* __restrict__ Wi, const float* __restrict__ bi,
                      const float* __restrict__ Wh, const float* __restrict__ bh)
{
    __shared__ float As[BK][BM];
    __shared__ float Bs[3][BK][BN];

    const int tid = threadIdx.x;
    const int m0 = blockIdx.y * BM;
    const int n0 = blockIdx.x * BN;

    const float* W[3] = {Wf, Wi, Wh};

    const int ty = tid >> 4;          // 0..15 (m dir)
    const int tx = tid & 15;          // 0..15 (n dir)

    // A-load mapping: 64 rows x 16 k, float4 per thread
    const int lr = tid >> 2;          // 0..63
    const int lk = (tid & 3) * 4;     // 0,4,8,12
    // B-load mapping: 16 k-rows x 64 n, float4 per thread
    const int wr = tid >> 4;          // 0..15
    const int wc = (tid & 15) * 4;    // 0..60

    float acc[3][4][4];
    #pragma unroll
    for (int j = 0; j < 3; j++)
        #pragma unroll
        for (int i = 0; i < 4; i++)
            #pragma unroll
            for (int n = 0; n < 4; n++) acc[j][i][n] = 0.f;

    for (int k0 = 0; k0 < DD; k0 += BK) {
        float4 av = *(const float4*)&x[(size_t)(m0 + lr)*DD + k0 + lk];
        As[lk+0][lr] = av.x; As[lk+1][lr] = av.y;
        As[lk+2][lr] = av.z; As[lk+3][lr] = av.w;
        #pragma unroll
        for (int j = 0; j < 3; j++) {
            float4 bv = *(const float4*)&W[j][(size_t)(k0 + wr)*HH + n0 + wc];
            *(float4*)&Bs[j][wr][wc] = bv;
        }
        __syncthreads();

        #pragma unroll
        for (int kk = 0; kk < BK; kk++) {
            float a[4];
            *(float4*)a = *(const float4*)&As[kk][ty*4];
            float b[3][4];
            #pragma unroll
            for (int j = 0; j < 3; j++)
                *(float4*)b[j] = *(const float4*)&Bs[j][kk][tx*4];
            #pragma unroll
            for (int j = 0; j < 3; j++)
                #pragma unroll
                for (int i = 0; i < 4; i++)
                    #pragma unroll
                    for (int n = 0; n < 4; n++)
                        acc[j][i][n] = fmaf(a[i], b[j][n], acc[j][i][n]);
        }
        __syncthreads();
    }

    // epilogue: gate math + store f, v
    float bfv[4], biv[4], bhv[4];
    *(float4*)bfv = *(const float4*)&bf[n0 + tx*4];
    *(float4*)biv = *(const float4*)&bi[n0 + tx*4];
    *(float4*)bhv = *(const float4*)&bh[n0 + tx*4];

    #pragma unroll
    for (int i = 0; i < 4; i++) {
        const size_t m = (size_t)(m0 + ty*4 + i);
        float fr[4], vr[4];
        #pragma unroll
        for (int n = 0; n < 4; n++) {
            float fpre = acc[0][i][n] + bfv[n];
            float ipre = acc[1][i][n] + biv[n];
            float hpre = acc[2][i][n] + bhv[n];
            float d  = sp(-fpre) - sp(-ipre);
            float ig = 1.f / (1.f + expf(-d));   // input gate  = sigmoid(d)
            float fg = 1.f / (1.f + expf(d));    // forget gate = sigmoid(-d)
            float g  = (hpre >= 0.f) ? (hpre + 0.5f)
                                     : 1.f / (1.f + expf(-hpre));
            fr[n] = fg;
            vr[n] = ig * g;
        }
        *(float4*)&g_f[m*HH + n0 + tx*4] = *(float4*)fr;
        *(float4*)&g_v[m*HH + n0 + tx*4] = *(float4*)vr;
    }
}

// ---------------------------------------------------------------------------
// Kernel 2: per-chunk affine aggregates. State (F,V): h_out = F*h_in + V.
// ---------------------------------------------------------------------------
__global__ __launch_bounds__(256)
void scan_chunk_kernel()
{
    const int ch = blockIdx.x * 256 + threadIdx.x;     // 0..2047
    const int b  = ch >> 9;
    const int hh = ch & (HH - 1);
    const int chunk = blockIdx.y;
    const size_t base = ((size_t)b*TT + (size_t)chunk*CL)*HH + hh;

    float F = 1.f, V = 0.f;
    #pragma unroll 4
    for (int t = 0; t < CL; t++) {
        float f = g_f[base + (size_t)t*HH];
        float v = g_v[base + (size_t)t*HH];
        V = fmaf(f, V, v);
        F = F * f;
    }
    g_cF[ch*NC + chunk] = F;
    g_cV[ch*NC + chunk] = V;
}

// ---------------------------------------------------------------------------
// Kernel 3: serial scan across chunk aggregates (tiny), also writes out[:,0,:]
// ---------------------------------------------------------------------------
__global__ __launch_bounds__(256)
void scan_top_kernel(const float* __restrict__ h0, float* __restrict__ out)
{
    const int ch = blockIdx.x * 256 + threadIdx.x;
    const int b  = ch >> 9;
    const int hh = ch & (HH - 1);

    float x = h0[(size_t)b*HH + hh];
    float h = (x >= 0.f) ? (x + 0.5f) : 1.f / (1.f + expf(-x));   // g(h_0)
    out[(size_t)b*(TT+1)*HH + hh] = h;                             // t = 0

    #pragma unroll
    for (int c = 0; c < NC; c++) {
        g_hin[ch*NC + c] = h;
        h = fmaf(g_cF[ch*NC + c], h, g_cV[ch*NC + c]);
    }
}

// ---------------------------------------------------------------------------
// Kernel 4: apply — re-scan each chunk with its incoming h, write outputs.
// ---------------------------------------------------------------------------
__global__ __launch_bounds__(256)
void scan_apply_kernel(float* __restrict__ out)
{
    const int ch = blockIdx.x * 256 + threadIdx.x;
    const int b  = ch >> 9;
    const int hh = ch & (HH - 1);
    const int chunk = blockIdx.y;
    const int t0 = chunk * CL;
    const size_t gbase = ((size_t)b*TT + t0)*HH + hh;
    const size_t obase = ((size_t)b*(TT+1) + t0 + 1)*HH + hh;

    float h = g_hin[ch*NC + chunk];
    #pragma unroll 4
    for (int t = 0; t < CL; t++) {
        float f = g_f[gbase + (size_t)t*HH];
        float v = g_v[gbase + (size_t)t*HH];
        h = fmaf(f, h, v);
        out[obase + (size_t)t*HH] = h;
    }
}

// ---------------------------------------------------------------------------
extern "C" void kernel_launch(void* const* d_in, const int* in_sizes, int n_in,
                              void* d_out, int out_size)
{
    const float* x  = (const float*)d_in[0];
    const float* h0 = (const float*)d_in[1];
    const float* Wf = (const float*)d_in[2];
    const float* bf = (const float*)d_in[3];
    const float* Wi = (const float*)d_in[4];
    const float* bi = (const float*)d_in[5];
    const float* Wh = (const float*)d_in[6];
    const float* bh = (const float*)d_in[7];
    float* out = (float*)d_out;

    dim3 gGemm(HH/BN, M_TOTAL/BM);            // (8, 512)
    gemm_gate_kernel<<<gGemm, 256>>>(x, Wf, bf, Wi, bi, Wh, bh);

    dim3 gScan(NCH/256, NC);                  // (8, 32)
    scan_chunk_kernel<<<gScan, 256>>>();
    scan_top_kernel<<<NCH/256, 256>>>(h0, out);
    scan_apply_kernel<<<gScan, 256>>>(out);
}

// round 3
// speedup vs baseline: 1.8831x; 1.8831x over previous
#include <cuda_runtime.h>
#include <cuda_bf16.h>
#include <math.h>
#include <stdint.h>

#define BB 4
#define TT 8192
#define DD 512
#define HH 512
#define M_TOTAL (BB*TT)        // 32768
#define NC 128                 // scan chunks
#define CL (TT/NC)             // 64 steps per chunk
#define NCH (BB*HH)            // 2048 channels

// ---------------- device scratch (allocation-free) ----------------
__device__ float          g_pre[3*(size_t)M_TOTAL*HH];  // pre-activations, 192MB
__device__ __nv_bfloat16  g_xhi[(size_t)M_TOTAL*DD];    // 32MB
__device__ __nv_bfloat16  g_xlo[(size_t)M_TOTAL*DD];    // 32MB
__device__ __nv_bfloat16  g_whi[3*DD*HH];               // [g][n][k] transposed
__device__ __nv_bfloat16  g_wlo[3*DD*HH];
__device__ float          g_cF[(size_t)NC*NCH];
__device__ float          g_cV[(size_t)NC*NCH];
__device__ float          g_hin[(size_t)NC*NCH];

__device__ __forceinline__ uint32_t smem_u32(const void* p) {
    uint32_t a;
    asm("{ .reg .u64 t; cvta.to.shared.u64 t, %1; cvt.u32.u64 %0, t; }" : "=r"(a) : "l"(p));
    return a;
}

#define LDM_X4(r0,r1,r2,r3,addr) \
    asm volatile("ldmatrix.sync.aligned.m8n8.x4.shared.b16 {%0,%1,%2,%3}, [%4];" \
        : "=r"(r0),"=r"(r1),"=r"(r2),"=r"(r3) : "r"(addr))

#define MMA_BF16(c,a,b) \
    asm volatile("mma.sync.aligned.m16n8k16.row.col.f32.bf16.bf16.f32 " \
        "{%0,%1,%2,%3},{%4,%5,%6,%7},{%8,%9},{%0,%1,%2,%3};" \
        : "+f"((c)[0]),"+f"((c)[1]),"+f"((c)[2]),"+f"((c)[3]) \
        : "r"((a)[0]),"r"((a)[1]),"r"((a)[2]),"r"((a)[3]),"r"((b)[0]),"r"((b)[1]))

// ---------------------------------------------------------------------------
// Prep 1: split x into bf16 hi/lo
// ---------------------------------------------------------------------------
__global__ __launch_bounds__(256)
void split_x_kernel(const float* __restrict__ x) {
    size_t i = ((size_t)blockIdx.x * 256 + threadIdx.x) * 4;
    float4 v = *(const float4*)(x + i);
    __nv_bfloat16 h0 = __float2bfloat16(v.x), h1 = __float2bfloat16(v.y);
    __nv_bfloat16 h2 = __float2bfloat16(v.z), h3 = __float2bfloat16(v.w);
    __nv_bfloat16 l0 = __float2bfloat16(v.x - __bfloat162float(h0));
    __nv_bfloat16 l1 = __float2bfloat16(v.y - __bfloat162float(h1));
    __nv_bfloat16 l2 = __float2bfloat16(v.z - __bfloat162float(h2));
    __nv_bfloat16 l3 = __float2bfloat16(v.w - __bfloat162float(h3));
    __nv_bfloat162* ph = (__nv_bfloat162*)(g_xhi + i);
    __nv_bfloat162* pl = (__nv_bfloat162*)(g_xlo + i);
    ph[0] = __nv_bfloat162(h0, h1); ph[1] = __nv_bfloat162(h2, h3);
    pl[0] = __nv_bfloat162(l0, l1); pl[1] = __nv_bfloat162(l2, l3);
}

// ---------------------------------------------------------------------------
// Prep 2: transpose + split W (out layout [g][n][k])
// ---------------------------------------------------------------------------
__global__ __launch_bounds__(256)
void split_w_kernel(const float* __restrict__ Wf, const float* __restrict__ Wi,
                    const float* __restrict__ Wh) {
    __shared__ float t[32][33];
    const float* W = (blockIdx.z == 0) ? Wf : (blockIdx.z == 1) ? Wi : Wh;
    int k0 = blockIdx.x * 32, n0 = blockIdx.y * 32;
    for (int i = threadIdx.y; i < 32; i += 8)
        t[i][threadIdx.x] = W[(size_t)(k0 + i) * HH + n0 + threadIdx.x];
    __syncthreads();
    for (int i = threadIdx.y; i < 32; i += 8) {
        float w = t[threadIdx.x][i];
        __nv_bfloat16 hi = __float2bfloat16(w);
        __nv_bfloat16 lo = __float2bfloat16(w - __bfloat162float(hi));
        size_t o = (size_t)blockIdx.z * DD * HH + (size_t)(n0 + i) * DD + k0 + threadIdx.x;
        g_whi[o] = hi;
        g_wlo[o] = lo;
    }
}

// ---------------------------------------------------------------------------
// Kernel 1: mma.sync bf16 split-GEMM. Per-CTA: M=128, N=128 (one gate),
// K_cat = 1536 (hi*hi | lo*hi | hi*lo), BK=32, 4-stage cp.async pipeline.
// Writes bias-added fp32 pre-activations to g_pre[gate].
// ---------------------------------------------------------------------------
#define STAGES 4
#define PITCH  80                    // 64B data + 16B pad; conflict-free
#define ASZ    (128*PITCH)           // 10240B
#define STAGE_BYTES (2*ASZ)          // 20480B (A + B)
#define GEMM_SMEM (STAGES*STAGE_BYTES)  // 81920B
#define NKT    48                    // 1536 / 32

__global__ __launch_bounds__(256)
void gemm_mma_kernel(const float* __restrict__ bf_, const float* __restrict__ bi_,
                     const float* __restrict__ bh_) {
    extern __shared__ char sm[];
    const uint32_t sb = smem_u32(sm);
    const int tid = threadIdx.x;
    const int m0 = blockIdx.y * 128;
    const int n0 = blockIdx.x * 128;
    const int gate = n0 >> 9;
    const int h0 = n0 & 511;

    const int wid = tid >> 5, lane = tid & 31;
    const int wm = wid & 3, wn = wid >> 2;      // warp tile 32(m) x 64(n)
    const int grp = lane >> 3, lrow = lane & 7;

    float acc[2][8][4];
    #pragma unroll
    for (int mt = 0; mt < 2; mt++)
        #pragma unroll
        for (int nt = 0; nt < 8; nt++)
            #pragma unroll
            for (int j = 0; j < 4; j++) acc[mt][nt][j] = 0.f;

    // --- async stage loader ---
    auto issue = [&](int kt) {
        const int st = kt & (STAGES - 1);
        const int seg = kt >> 4;                 // 0,1,2
        const int kin = (kt << 5) & 511;
        const __nv_bfloat16* __restrict__ asrc = (seg == 1) ? g_xlo : g_xhi;
        const __nv_bfloat16* __restrict__ bsrc =
            ((seg == 2) ? g_wlo : g_whi) + (size_t)gate * DD * HH;
        const uint32_t sA = sb + st * STAGE_BYTES;
        const uint32_t sB = sA + ASZ;
        #pragma unroll
        for (int it = 0; it < 2; it++) {
            int idx = tid + it * 256;           // 0..511
            int r = idx >> 2, c = idx & 3;
            const void* ga = asrc + (size_t)(m0 + r) * 512 + kin + c * 8;
            asm volatile("cp.async.cg.shared.global [%0], [%1], 16;"
                         :: "r"(sA + r * PITCH + c * 16), "l"(ga));
            const void* gb = bsrc + (size_t)(h0 + r) * 512 + kin + c * 8;
            asm volatile("cp.async.cg.shared.global [%0], [%1], 16;"
                         :: "r"(sB + r * PITCH + c * 16), "l"(gb));
        }
        asm volatile("cp.async.commit_group;" ::: "memory");
    };

    issue(0); issue(1); issue(2);

    #pragma unroll 1
    for (int kt = 0; kt < NKT; kt++) {
        asm volatile("cp.async.wait_group 2;" ::: "memory");
        __syncthreads();
        if (kt + 3 < NKT) issue(kt + 3);

        const uint32_t sA = sb + (kt & (STAGES - 1)) * STAGE_BYTES;
        const uint32_t sB = sA + ASZ;

        #pragma unroll
        for (int kk = 0; kk < 2; kk++) {
            uint32_t a[2][4];
            #pragma unroll
            for (int mt = 0; mt < 2; mt++) {
                uint32_t addr = sA + (uint32_t)(wm * 32 + mt * 16 + lrow + (grp & 1) * 8) * PITCH
                                   + (uint32_t)(kk * 2 + (grp >> 1)) * 16;
                LDM_X4(a[mt][0], a[mt][1], a[mt][2], a[mt][3], addr);
            }
            uint32_t b[8][2];
            #pragma unroll
            for (int nq = 0; nq < 4; nq++) {
                uint32_t addr = sB + (uint32_t)(wn * 64 + nq * 16 + lrow + (grp >> 1) * 8) * PITCH
                                   + (uint32_t)(kk * 2 + (grp & 1)) * 16;
                uint32_t r0, r1, r2, r3;
                LDM_X4(r0, r1, r2, r3, addr);
                b[nq * 2][0] = r0;   b[nq * 2][1] = r1;
                b[nq * 2 + 1][0] = r2; b[nq * 2 + 1][1] = r3;
            }
            #pragma unroll
            for (int mt = 0; mt < 2; mt++)
                #pragma unroll
                for (int nt = 0; nt < 8; nt++)
                    MMA_BF16(acc[mt][nt], a[mt], b[nt]);
        }
    }

    // epilogue: bias add + store fp32 pre-activations
    const float* __restrict__ bias = (gate == 0) ? bf_ : (gate == 1) ? bi_ : bh_;
    float* __restrict__ plane = g_pre + (size_t)gate * M_TOTAL * HH;
    #pragma unroll
    for (int mt = 0; mt < 2; mt++) {
        #pragma unroll
        for (int nt = 0; nt < 8; nt++) {
            int m = m0 + wm * 32 + mt * 16 + (lane >> 2);
            int h = h0 + wn * 64 + nt * 8 + 2 * (lane & 3);
            float b0 = __ldg(&bias[h]), b1 = __ldg(&bias[h + 1]);
            float2 v0 = make_float2(acc[mt][nt][0] + b0, acc[mt][nt][1] + b1);
            float2 v1 = make_float2(acc[mt][nt][2] + b0, acc[mt][nt][3] + b1);
            *(float2*)&plane[(size_t)m * HH + h] = v0;
            *(float2*)&plane[(size_t)(m + 8) * HH + h] = v1;
        }
    }
}

// ---------------------------------------------------------------------------
// Gate math from pre-activations (closed form, no softplus):
//   u = 1+e^{-f_pre}, w = 1+e^{-i_pre}:  fg = w/(u+w), ig = u/(u+w)
//   g(x) = x>=0 ? x+0.5 : sigmoid(x);   v = ig * g(h_pre)
// ---------------------------------------------------------------------------
__device__ __forceinline__ void gate_fv(float fpre, float ipre, float hpre,
                                        float& f, float& v) {
    float u = 1.f + __expf(-fpre);
    float w = 1.f + __expf(-ipre);
    float r = __fdividef(1.f, u + w);
    f = w * r;
    float ig = u * r;
    float g = (hpre >= 0.f) ? (hpre + 0.5f)
                            : __fdividef(1.f, 1.f + __expf(-hpre));
    v = ig * g;
}

#define PL ((size_t)M_TOTAL*HH)

// ---------------------------------------------------------------------------
// Kernel 2: per-chunk affine aggregates (recompute gates from pre)
// ---------------------------------------------------------------------------
__global__ __launch_bounds__(256)
void scan_chunk_kernel() {
    const int ch = blockIdx.x * 256 + threadIdx.x;
    const int b = ch >> 9, hh = ch & (HH - 1);
    const int chunk = blockIdx.y;
    const size_t base = ((size_t)b * TT + (size_t)chunk * CL) * HH + hh;

    float F = 1.f, V = 0.f;
    #pragma unroll 4
    for (int t = 0; t < CL; t++) {
        size_t o = base + (size_t)t * HH;
        float f, v;
        gate_fv(g_pre[o], g_pre[PL + o], g_pre[2 * PL + o], f, v);
        V = fmaf(f, V, v);
        F = F * f;
    }
    g_cF[(size_t)chunk * NCH + ch] = F;
    g_cV[(size_t)chunk * NCH + ch] = V;
}

// ---------------------------------------------------------------------------
// Kernel 3: serial cross-chunk scan + out[:,0,:]
// ---------------------------------------------------------------------------
__global__ __launch_bounds__(256)
void scan_top_kernel(const float* __restrict__ h0, float* __restrict__ out) {
    const int ch = blockIdx.x * 256 + threadIdx.x;
    const int b = ch >> 9, hh = ch & (HH - 1);

    float x = h0[(size_t)b * HH + hh];
    float h = (x >= 0.f) ? (x + 0.5f) : __fdividef(1.f, 1.f + __expf(-x));
    out[(size_t)b * (TT + 1) * HH + hh] = h;

    #pragma unroll 8
    for (int c = 0; c < NC; c++) {
        g_hin[(size_t)c * NCH + ch] = h;
        h = fmaf(g_cF[(size_t)c * NCH + ch], h, g_cV[(size_t)c * NCH + ch]);
    }
}

// ---------------------------------------------------------------------------
// Kernel 4: apply (recompute gates, write outputs)
// ---------------------------------------------------------------------------
__global__ __launch_bounds__(256)
void scan_apply_kernel(float* __restrict__ out) {
    const int ch = blockIdx.x * 256 + threadIdx.x;
    const int b = ch >> 9, hh = ch & (HH - 1);
    const int chunk = blockIdx.y;
    const int t0 = chunk * CL;
    const size_t gbase = ((size_t)b * TT + t0) * HH + hh;
    const size_t obase = ((size_t)b * (TT + 1) + t0 + 1) * HH + hh;

    float h = g_hin[(size_t)chunk * NCH + ch];
    #pragma unroll 4
    for (int t = 0; t < CL; t++) {
        size_t o = gbase + (size_t)t * HH;
        float f, v;
        gate_fv(g_pre[o], g_pre[PL + o], g_pre[2 * PL + o], f, v);
        h = fmaf(f, h, v);
        out[obase + (size_t)t * HH] = h;
    }
}

// ---------------------------------------------------------------------------
extern "C" void kernel_launch(void* const* d_in, const int* in_sizes, int n_in,
                              void* d_out, int out_size) {
    const float* x  = (const float*)d_in[0];
    const float* h0 = (const float*)d_in[1];
    const float* Wf = (const float*)d_in[2];
    const float* bf = (const float*)d_in[3];
    const float* Wi = (const float*)d_in[4];
    const float* bi = (const float*)d_in[5];
    const float* Wh = (const float*)d_in[6];
    const float* bh = (const float*)d_in[7];
    float* out = (float*)d_out;

    cudaFuncSetAttribute(gemm_mma_kernel,
                         cudaFuncAttributeMaxDynamicSharedMemorySize, GEMM_SMEM);

    split_x_kernel<<<(size_t)M_TOTAL * DD / 4 / 256, 256>>>(x);
    {
        dim3 g(DD / 32, HH / 32, 3);
        split_w_kernel<<<g, dim3(32, 8)>>>(Wf, Wi, Wh);
    }
    {
        dim3 g(3 * HH / 128, M_TOTAL / 128);   // (12, 256)
        gemm_mma_kernel<<<g, 256, GEMM_SMEM>>>(bf, bi, bh);
    }
    {
        dim3 g(NCH / 256, NC);                 // (8, 128)
        scan_chunk_kernel<<<g, 256>>>();
        scan_top_kernel<<<NCH / 256, 256>>>(h0, out);
        scan_apply_kernel<<<g, 256>>>(out);
    }
}

// round 4
// speedup vs baseline: 2.8498x; 1.5134x over previous
#include <cuda_runtime.h>
#include <cuda_fp16.h>
#include <math.h>
#include <stdint.h>

#define BB 4
#define TT 8192
#define DD 512
#define HH 512
#define M_TOTAL (BB*TT)        // 32768
#define NC 128                 // scan chunks
#define CL (TT/NC)             // 64 steps per chunk
#define NCH (BB*HH)            // 2048 channels

// ---------------- device scratch (allocation-free) ----------------
__device__ float  g_f[(size_t)M_TOTAL*HH];    // forget gate (64MB)
__device__ float  g_v[(size_t)M_TOTAL*HH];    // i*g value   (64MB)
__device__ __half g_xhi[(size_t)M_TOTAL*DD];  // 32MB
__device__ __half g_xlo[(size_t)M_TOTAL*DD];  // 32MB
__device__ __half g_w[3*DD*HH];               // [g][n][k] transposed, fp16
__device__ float  g_cF[(size_t)NC*NCH];
__device__ float  g_cV[(size_t)NC*NCH];
__device__ float  g_hin[(size_t)NC*NCH];

__device__ __forceinline__ uint32_t smem_u32(const void* p) {
    uint32_t a;
    asm("{ .reg .u64 t; cvta.to.shared.u64 t, %1; cvt.u32.u64 %0, t; }" : "=r"(a) : "l"(p));
    return a;
}

#define LDM_X4(r0,r1,r2,r3,addr) \
    asm volatile("ldmatrix.sync.aligned.m8n8.x4.shared.b16 {%0,%1,%2,%3}, [%4];" \
        : "=r"(r0),"=r"(r1),"=r"(r2),"=r"(r3) : "r"(addr))

#define MMA_FP16(c,a,b) \
    asm volatile("mma.sync.aligned.m16n8k16.row.col.f32.f16.f16.f32 " \
        "{%0,%1,%2,%3},{%4,%5,%6,%7},{%8,%9},{%0,%1,%2,%3};" \
        : "+f"((c)[0]),"+f"((c)[1]),"+f"((c)[2]),"+f"((c)[3]) \
        : "r"((a)[0]),"r"((a)[1]),"r"((a)[2]),"r"((a)[3]),"r"((b)[0]),"r"((b)[1]))

// ---------------------------------------------------------------------------
// Prep 1: split x into fp16 hi/lo  (x = hi + lo exactly to ~2^-22)
// ---------------------------------------------------------------------------
__global__ __launch_bounds__(256)
void split_x_kernel(const float* __restrict__ x) {
    size_t i = ((size_t)blockIdx.x * 256 + threadIdx.x) * 4;
    float4 v = *(const float4*)(x + i);
    __half h0 = __float2half(v.x), h1 = __float2half(v.y);
    __half h2 = __float2half(v.z), h3 = __float2half(v.w);
    __half l0 = __float2half(v.x - __half2float(h0));
    __half l1 = __float2half(v.y - __half2float(h1));
    __half l2 = __float2half(v.z - __half2float(h2));
    __half l3 = __float2half(v.w - __half2float(h3));
    __half2* ph = (__half2*)(g_xhi + i);
    __half2* pl = (__half2*)(g_xlo + i);
    ph[0] = __half2(h0, h1); ph[1] = __half2(h2, h3);
    pl[0] = __half2(l0, l1); pl[1] = __half2(l2, l3);
}

// ---------------------------------------------------------------------------
// Prep 2: transpose W to fp16, layout [g][n][k]
// ---------------------------------------------------------------------------
__global__ __launch_bounds__(256)
void split_w_kernel(const float* __restrict__ Wf, const float* __restrict__ Wi,
                    const float* __restrict__ Wh) {
    __shared__ float t[32][33];
    const float* W = (blockIdx.z == 0) ? Wf : (blockIdx.z == 1) ? Wi : Wh;
    int k0 = blockIdx.x * 32, n0 = blockIdx.y * 32;
    for (int i = threadIdx.y; i < 32; i += 8)
        t[i][threadIdx.x] = W[(size_t)(k0 + i) * HH + n0 + threadIdx.x];
    __syncthreads();
    for (int i = threadIdx.y; i < 32; i += 8) {
        size_t o = (size_t)blockIdx.z * DD * HH + (size_t)(n0 + i) * DD + k0 + threadIdx.x;
        g_w[o] = __float2half(t[threadIdx.x][i]);
    }
}

// ---------------------------------------------------------------------------
// Gate math (closed form, no softplus):
//   u=1+e^{-f_pre}, w=1+e^{-i_pre}:  fg=w/(u+w), ig=u/(u+w)
//   g(x)= x>=0 ? x+0.5 : sigmoid(x);  v = ig*g(h_pre)
// ---------------------------------------------------------------------------
__device__ __forceinline__ void gate_fv(float fpre, float ipre, float hpre,
                                        float& f, float& v) {
    float u = 1.f + __expf(-fpre);
    float w = 1.f + __expf(-ipre);
    float r = __fdividef(1.f, u + w);
    f = w * r;
    float ig = u * r;
    float g = (hpre >= 0.f) ? (hpre + 0.5f)
                            : __fdividef(1.f, 1.f + __expf(-hpre));
    v = ig * g;
}

// ---------------------------------------------------------------------------
// Kernel 1: fused 3-gate fp16 GEMM + gate epilogue.
// CTA: M=128, N=64, all 3 gates. K-stage = {x_hi 128r, x_lo 128r, W 3x64r} x 32k.
// acc += x_hi.B + x_lo.B  (== x.B with fp32-split x). Epilogue writes g_f, g_v.
// ---------------------------------------------------------------------------
#define NKT    16                    // 512 / 32
#define STAGES 3
#define PITCH  80                    // 64B data + 16B pad; conflict-free
#define ROWS_ST 448                  // 128 + 128 + 192
#define STAGE_BYTES (ROWS_ST*PITCH)  // 35840
#define GEMM_SMEM (STAGES*STAGE_BYTES)  // 107520
#define OFF_ALO (128*PITCH)
#define OFF_B   (256*PITCH)

__global__ __launch_bounds__(512)
void gemm_mma_kernel(const float* __restrict__ bf_, const float* __restrict__ bi_,
                     const float* __restrict__ bh_) {
    extern __shared__ char sm[];
    const uint32_t sb = smem_u32(sm);
    const int tid = threadIdx.x;
    const int m0 = blockIdx.y * 128;
    const int h0 = blockIdx.x * 64;

    const int wid = tid >> 5, lane = tid & 31;
    const int wm = wid & 3, wn = wid >> 2;      // 4m x 4n warps; warp tile 32m x 16n x 3g
    const int grp = lane >> 3, lrow = lane & 7;

    float acc[3][2][2][4];
    #pragma unroll
    for (int g = 0; g < 3; g++)
        #pragma unroll
        for (int mt = 0; mt < 2; mt++)
            #pragma unroll
            for (int nt = 0; nt < 2; nt++)
                #pragma unroll
                for (int j = 0; j < 4; j++) acc[g][mt][nt][j] = 0.f;

    auto issue = [&](int kt) {
        const uint32_t sst = sb + (kt % STAGES) * STAGE_BYTES;
        const int kin = kt * 32;
        #pragma unroll
        for (int i = tid; i < 1792; i += 512) {
            int r = i >> 2, c = i & 3;
            const __half* src;
            if (r < 128)       src = g_xhi + (size_t)(m0 + r) * 512 + kin;
            else if (r < 256)  src = g_xlo + (size_t)(m0 + r - 128) * 512 + kin;
            else {
                int rr = r - 256;
                src = g_w + (size_t)(rr >> 6) * DD * HH
                          + (size_t)(h0 + (rr & 63)) * 512 + kin;
            }
            asm volatile("cp.async.cg.shared.global [%0], [%1], 16;"
                         :: "r"(sst + r * PITCH + c * 16), "l"(src + c * 8));
        }
        asm volatile("cp.async.commit_group;" ::: "memory");
    };

    issue(0); issue(1);

    #pragma unroll 1
    for (int kt = 0; kt < NKT; kt++) {
        asm volatile("cp.async.wait_group 1;" ::: "memory");
        __syncthreads();
        if (kt + 2 < NKT) issue(kt + 2);

        const uint32_t sst = sb + (kt % STAGES) * STAGE_BYTES;

        #pragma unroll
        for (int kk = 0; kk < 2; kk++) {
            const uint32_t acol = (uint32_t)(kk * 2 + (grp >> 1)) * 16;
            const uint32_t bcol = (uint32_t)(kk * 2 + (grp & 1)) * 16;
            uint32_t ah[2][4], al[2][4];
            #pragma unroll
            for (int mt = 0; mt < 2; mt++) {
                uint32_t rrow = (uint32_t)(wm * 32 + mt * 16 + lrow + (grp & 1) * 8) * PITCH;
                LDM_X4(ah[mt][0], ah[mt][1], ah[mt][2], ah[mt][3], sst + rrow + acol);
                LDM_X4(al[mt][0], al[mt][1], al[mt][2], al[mt][3], sst + OFF_ALO + rrow + acol);
            }
            uint32_t b[3][2][2];
            #pragma unroll
            for (int g = 0; g < 3; g++) {
                uint32_t addr = sst + OFF_B
                    + (uint32_t)(g * 64 + wn * 16 + lrow + (grp >> 1) * 8) * PITCH + bcol;
                uint32_t r0, r1, r2, r3;
                LDM_X4(r0, r1, r2, r3, addr);
                b[g][0][0] = r0; b[g][0][1] = r1;
                b[g][1][0] = r2; b[g][1][1] = r3;
            }
            #pragma unroll
            for (int g = 0; g < 3; g++)
                #pragma unroll
                for (int mt = 0; mt < 2; mt++)
                    #pragma unroll
                    for (int nt = 0; nt < 2; nt++) {
                        MMA_FP16(acc[g][mt][nt], ah[mt], b[g][nt]);
                        MMA_FP16(acc[g][mt][nt], al[mt], b[g][nt]);
                    }
        }
    }

    // epilogue: gate math, write f & v
    #pragma unroll
    for (int mt = 0; mt < 2; mt++) {
        #pragma unroll
        for (int nt = 0; nt < 2; nt++) {
            const int m = m0 + wm * 32 + mt * 16 + (lane >> 2);
            const int h = h0 + wn * 16 + nt * 8 + 2 * (lane & 3);
            const float b0f = __ldg(&bf_[h]), b1f = __ldg(&bf_[h + 1]);
            const float b0i = __ldg(&bi_[h]), b1i = __ldg(&bi_[h + 1]);
            const float b0h = __ldg(&bh_[h]), b1h = __ldg(&bh_[h + 1]);
            #pragma unroll
            for (int half_ = 0; half_ < 2; half_++) {      // rows m, m+8
                const int mm = m + half_ * 8;
                float f0, v0, f1, v1;
                gate_fv(acc[0][mt][nt][half_*2+0] + b0f,
                        acc[1][mt][nt][half_*2+0] + b0i,
                        acc[2][mt][nt][half_*2+0] + b0h, f0, v0);
                gate_fv(acc[0][mt][nt][half_*2+1] + b1f,
                        acc[1][mt][nt][half_*2+1] + b1i,
                        acc[2][mt][nt][half_*2+1] + b1h, f1, v1);
                *(float2*)&g_f[(size_t)mm * HH + h] = make_float2(f0, f1);
                *(float2*)&g_v[(size_t)mm * HH + h] = make_float2(v0, v1);
            }
        }
    }
}

// ---------------------------------------------------------------------------
// Kernel 2: per-chunk affine aggregates (h_out = F*h_in + V)
// ---------------------------------------------------------------------------
__global__ __launch_bounds__(256)
void scan_chunk_kernel() {
    const int ch = blockIdx.x * 256 + threadIdx.x;
    const int b = ch >> 9, hh = ch & (HH - 1);
    const int chunk = blockIdx.y;
    const size_t base = ((size_t)b * TT + (size_t)chunk * CL) * HH + hh;

    float F = 1.f, V = 0.f;
    #pragma unroll 8
    for (int t = 0; t < CL; t++) {
        float f = g_f[base + (size_t)t * HH];
        float v = g_v[base + (size_t)t * HH];
        V = fmaf(f, V, v);
        F = F * f;
    }
    g_cF[(size_t)chunk * NCH + ch] = F;
    g_cV[(size_t)chunk * NCH + ch] = V;
}

// ---------------------------------------------------------------------------
// Kernel 3: serial cross-chunk scan + out[:,0,:]
// ---------------------------------------------------------------------------
__global__ __launch_bounds__(256)
void scan_top_kernel(const float* __restrict__ h0, float* __restrict__ out) {
    const int ch = blockIdx.x * 256 + threadIdx.x;
    const int b = ch >> 9, hh = ch & (HH - 1);

    float x = h0[(size_t)b * HH + hh];
    float h = (x >= 0.f) ? (x + 0.5f) : __fdividef(1.f, 1.f + __expf(-x));
    out[(size_t)b * (TT + 1) * HH + hh] = h;

    #pragma unroll 8
    for (int c = 0; c < NC; c++) {
        g_hin[(size_t)c * NCH + ch] = h;
        h = fmaf(g_cF[(size_t)c * NCH + ch], h, g_cV[(size_t)c * NCH + ch]);
    }
}

// ---------------------------------------------------------------------------
// Kernel 4: apply
// ---------------------------------------------------------------------------
__global__ __launch_bounds__(256)
void scan_apply_kernel(float* __restrict__ out) {
    const int ch = blockIdx.x * 256 + threadIdx.x;
    const int b = ch >> 9, hh = ch & (HH - 1);
    const int chunk = blockIdx.y;
    const int t0 = chunk * CL;
    const size_t gbase = ((size_t)b * TT + t0) * HH + hh;
    const size_t obase = ((size_t)b * (TT + 1) + t0 + 1) * HH + hh;

    float h = g_hin[(size_t)chunk * NCH + ch];
    #pragma unroll 8
    for (int t = 0; t < CL; t++) {
        float f = g_f[gbase + (size_t)t * HH];
        float v = g_v[gbase + (size_t)t * HH];
        h = fmaf(f, h, v);
        out[obase + (size_t)t * HH] = h;
    }
}

// ---------------------------------------------------------------------------
extern "C" void kernel_launch(void* const* d_in, const int* in_sizes, int n_in,
                              void* d_out, int out_size) {
    const float* x  = (const float*)d_in[0];
    const float* h0 = (const float*)d_in[1];
    const float* Wf = (const float*)d_in[2];
    const float* bf = (const float*)d_in[3];
    const float* Wi = (const float*)d_in[4];
    const float* bi = (const float*)d_in[5];
    const float* Wh = (const float*)d_in[6];
    const float* bh = (const float*)d_in[7];
    float* out = (float*)d_out;

    cudaFuncSetAttribute(gemm_mma_kernel,
                         cudaFuncAttributeMaxDynamicSharedMemorySize, GEMM_SMEM);

    split_x_kernel<<<(size_t)M_TOTAL * DD / 4 / 256, 256>>>(x);
    {
        dim3 g(DD / 32, HH / 32, 3);
        split_w_kernel<<<g, dim3(32, 8)>>>(Wf, Wi, Wh);
    }
    {
        dim3 g(HH / 64, M_TOTAL / 128);    // (8, 256)
        gemm_mma_kernel<<<g, 512, GEMM_SMEM>>>(bf, bi, bh);
    }
    {
        dim3 g(NCH / 256, NC);             // (8, 128)
        scan_chunk_kernel<<<g, 256>>>();
        scan_top_kernel<<<NCH / 256, 256>>>(h0, out);
        scan_apply_kernel<<<g, 256>>>(out);
    }
}

// round 5
// speedup vs baseline: 4.2363x; 1.4865x over previous
#include <cuda_runtime.h>
#include <cuda_fp16.h>
#include <math.h>
#include <stdint.h>

#define BB 4
#define TT 8192
#define DD 512
#define HH 512
#define M_TOTAL (BB*TT)        // 32768
#define NC 128                 // scan chunks
#define CL (TT/NC)             // 64 steps per chunk
#define NCH (BB*HH)            // 2048 channels

// ---------------- device scratch (allocation-free) ----------------
__device__ __half2 g_fv[(size_t)M_TOTAL*HH];  // packed {f, v}, 64MB
__device__ __half  g_x[(size_t)M_TOTAL*DD];   // fp16 x, 32MB
__device__ __half  g_w[3*DD*HH];              // [g][n][k] transposed, fp16
__device__ float   g_cF[(size_t)NC*NCH];
__device__ float   g_cV[(size_t)NC*NCH];
__device__ float   g_hin[(size_t)NC*NCH];

__device__ __forceinline__ uint32_t smem_u32(const void* p) {
    uint32_t a;
    asm("{ .reg .u64 t; cvta.to.shared.u64 t, %1; cvt.u32.u64 %0, t; }" : "=r"(a) : "l"(p));
    return a;
}

#define LDM_X4(r0,r1,r2,r3,addr) \
    asm volatile("ldmatrix.sync.aligned.m8n8.x4.shared.b16 {%0,%1,%2,%3}, [%4];" \
        : "=r"(r0),"=r"(r1),"=r"(r2),"=r"(r3) : "r"(addr))

#define MMA_FP16(c,a,b) \
    asm volatile("mma.sync.aligned.m16n8k16.row.col.f32.f16.f16.f32 " \
        "{%0,%1,%2,%3},{%4,%5,%6,%7},{%8,%9},{%0,%1,%2,%3};" \
        : "+f"((c)[0]),"+f"((c)[1]),"+f"((c)[2]),"+f"((c)[3]) \
        : "r"((a)[0]),"r"((a)[1]),"r"((a)[2]),"r"((a)[3]),"r"((b)[0]),"r"((b)[1]))

struct alignas(8) h2x2 { __half2 a, b; };

// ---------------------------------------------------------------------------
// Prep 1: convert x to fp16
// ---------------------------------------------------------------------------
__global__ __launch_bounds__(256)
void cvt_x_kernel(const float* __restrict__ x) {
    size_t i = ((size_t)blockIdx.x * 256 + threadIdx.x) * 8;
    float4 v0 = *(const float4*)(x + i);
    float4 v1 = *(const float4*)(x + i + 4);
    h2x2 o0, o1;
    o0.a = __floats2half2_rn(v0.x, v0.y);
    o0.b = __floats2half2_rn(v0.z, v0.w);
    o1.a = __floats2half2_rn(v1.x, v1.y);
    o1.b = __floats2half2_rn(v1.z, v1.w);
    ((h2x2*)(g_x + i))[0] = o0;
    ((h2x2*)(g_x + i))[1] = o1;
}

// ---------------------------------------------------------------------------
// Prep 2: transpose W to fp16, layout [g][n][k]
// ---------------------------------------------------------------------------
__global__ __launch_bounds__(256)
void split_w_kernel(const float* __restrict__ Wf, const float* __restrict__ Wi,
                    const float* __restrict__ Wh) {
    __shared__ float t[32][33];
    const float* W = (blockIdx.z == 0) ? Wf : (blockIdx.z == 1) ? Wi : Wh;
    int k0 = blockIdx.x * 32, n0 = blockIdx.y * 32;
    for (int i = threadIdx.y; i < 32; i += 8)
        t[i][threadIdx.x] = W[(size_t)(k0 + i) * HH + n0 + threadIdx.x];
    __syncthreads();
    for (int i = threadIdx.y; i < 32; i += 8) {
        size_t o = (size_t)blockIdx.z * DD * HH + (size_t)(n0 + i) * DD + k0 + threadIdx.x;
        g_w[o] = __float2half(t[threadIdx.x][i]);
    }
}

// ---------------------------------------------------------------------------
// Gate math: u=1+e^{-f_pre}, w=1+e^{-i_pre}: fg=w/(u+w), ig=u/(u+w)
//            g(x)= x>=0 ? x+0.5 : sigmoid(x);  v = ig*g(h_pre)
// ---------------------------------------------------------------------------
__device__ __forceinline__ void gate_fv(float fpre, float ipre, float hpre,
                                        float& f, float& v) {
    float u = 1.f + __expf(-fpre);
    float w = 1.f + __expf(-ipre);
    float r = __fdividef(1.f, u + w);
    f = w * r;
    float ig = u * r;
    float g = (hpre >= 0.f) ? (hpre + 0.5f)
                            : __fdividef(1.f, 1.f + __expf(-hpre));
    v = ig * g;
}

// ---------------------------------------------------------------------------
// Kernel 1: fused 3-gate fp16 GEMM + gate epilogue.
// CTA: M=128, N=64, 3 gates. K-stage = {x 128r, W 3x64r} x 32k, 4-stage pipe.
// ---------------------------------------------------------------------------
#define NKT    16                    // 512 / 32
#define STAGES 4
#define PITCH  80                    // 64B data + 16B pad; conflict-free
#define ROWS_ST 320                  // 128 + 192
#define STAGE_BYTES (ROWS_ST*PITCH)  // 25600
#define GEMM_SMEM (STAGES*STAGE_BYTES)  // 102400
#define OFF_B   (128*PITCH)

__global__ __launch_bounds__(512)
void gemm_mma_kernel(const float* __restrict__ bf_, const float* __restrict__ bi_,
                     const float* __restrict__ bh_) {
    extern __shared__ char sm[];
    const uint32_t sb = smem_u32(sm);
    const int tid = threadIdx.x;
    const int m0 = blockIdx.y * 128;
    const int h0 = blockIdx.x * 64;

    const int wid = tid >> 5, lane = tid & 31;
    const int wm = wid & 3, wn = wid >> 2;      // 4m x 4n warps; warp tile 32m x 16n x 3g
    const int grp = lane >> 3, lrow = lane & 7;

    float acc[3][2][2][4];
    #pragma unroll
    for (int g = 0; g < 3; g++)
        #pragma unroll
        for (int mt = 0; mt < 2; mt++)
            #pragma unroll
            for (int nt = 0; nt < 2; nt++)
                #pragma unroll
                for (int j = 0; j < 4; j++) acc[g][mt][nt][j] = 0.f;

    auto issue = [&](int kt) {
        const uint32_t sst = sb + (kt & (STAGES - 1)) * STAGE_BYTES;
        const int kin = kt * 32;
        #pragma unroll
        for (int i = tid; i < 1280; i += 512) {
            int r = i >> 2, c = i & 3;
            const __half* src;
            if (r < 128) src = g_x + (size_t)(m0 + r) * 512 + kin;
            else {
                int rr = r - 128;
                src = g_w + (size_t)(rr >> 6) * DD * HH
                          + (size_t)(h0 + (rr & 63)) * 512 + kin;
            }
            asm volatile("cp.async.cg.shared.global [%0], [%1], 16;"
                         :: "r"(sst + r * PITCH + c * 16), "l"(src + c * 8));
        }
        asm volatile("cp.async.commit_group;" ::: "memory");
    };

    issue(0); issue(1); issue(2);

    #pragma unroll 1
    for (int kt = 0; kt < NKT; kt++) {
        asm volatile("cp.async.wait_group 2;" ::: "memory");
        __syncthreads();
        if (kt + 3 < NKT) issue(kt + 3);

        const uint32_t sst = sb + (kt & (STAGES - 1)) * STAGE_BYTES;

        #pragma unroll
        for (int kk = 0; kk < 2; kk++) {
            const uint32_t acol = (uint32_t)(kk * 2 + (grp >> 1)) * 16;
            const uint32_t bcol = (uint32_t)(kk * 2 + (grp & 1)) * 16;
            uint32_t a[2][4];
            #pragma unroll
            for (int mt = 0; mt < 2; mt++) {
                uint32_t rrow = (uint32_t)(wm * 32 + mt * 16 + lrow + (grp & 1) * 8) * PITCH;
                LDM_X4(a[mt][0], a[mt][1], a[mt][2], a[mt][3], sst + rrow + acol);
            }
            uint32_t b[3][2][2];
            #pragma unroll
            for (int g = 0; g < 3; g++) {
                uint32_t addr = sst + OFF_B
                    + (uint32_t)(g * 64 + wn * 16 + lrow + (grp >> 1) * 8) * PITCH + bcol;
                uint32_t r0, r1, r2, r3;
                LDM_X4(r0, r1, r2, r3, addr);
                b[g][0][0] = r0; b[g][0][1] = r1;
                b[g][1][0] = r2; b[g][1][1] = r3;
            }
            #pragma unroll
            for (int g = 0; g < 3; g++)
                #pragma unroll
                for (int mt = 0; mt < 2; mt++)
                    #pragma unroll
                    for (int nt = 0; nt < 2; nt++)
                        MMA_FP16(acc[g][mt][nt], a[mt], b[g][nt]);
        }
    }

    // epilogue: gate math, write packed {f,v}
    #pragma unroll
    for (int mt = 0; mt < 2; mt++) {
        #pragma unroll
        for (int nt = 0; nt < 2; nt++) {
            const int m = m0 + wm * 32 + mt * 16 + (lane >> 2);
            const int h = h0 + wn * 16 + nt * 8 + 2 * (lane & 3);
            const float b0f = __ldg(&bf_[h]), b1f = __ldg(&bf_[h + 1]);
            const float b0i = __ldg(&bi_[h]), b1i = __ldg(&bi_[h + 1]);
            const float b0h = __ldg(&bh_[h]), b1h = __ldg(&bh_[h + 1]);
            #pragma unroll
            for (int half_ = 0; half_ < 2; half_++) {      // rows m, m+8
                const int mm = m + half_ * 8;
                float f0, v0, f1, v1;
                gate_fv(acc[0][mt][nt][half_*2+0] + b0f,
                        acc[1][mt][nt][half_*2+0] + b0i,
                        acc[2][mt][nt][half_*2+0] + b0h, f0, v0);
                gate_fv(acc[0][mt][nt][half_*2+1] + b1f,
                        acc[1][mt][nt][half_*2+1] + b1i,
                        acc[2][mt][nt][half_*2+1] + b1h, f1, v1);
                h2x2 pk;
                pk.a = __floats2half2_rn(f0, v0);
                pk.b = __floats2half2_rn(f1, v1);
                *(h2x2*)&g_fv[(size_t)mm * HH + h] = pk;
            }
        }
    }
}

// ---------------------------------------------------------------------------
// Kernel 2: per-chunk affine aggregates (h_out = F*h_in + V)
// ---------------------------------------------------------------------------
__global__ __launch_bounds__(256)
void scan_chunk_kernel() {
    const int ch = blockIdx.x * 256 + threadIdx.x;
    const int b = ch >> 9, hh = ch & (HH - 1);
    const int chunk = blockIdx.y;
    const size_t base = ((size_t)b * TT + (size_t)chunk * CL) * HH + hh;

    float F = 1.f, V = 0.f;
    #pragma unroll 8
    for (int t = 0; t < CL; t++) {
        float2 fv = __half22float2(g_fv[base + (size_t)t * HH]);
        V = fmaf(fv.x, V, fv.y);
        F = F * fv.x;
    }
    g_cF[(size_t)chunk * NCH + ch] = F;
    g_cV[(size_t)chunk * NCH + ch] = V;
}

// ---------------------------------------------------------------------------
// Kernel 3: serial cross-chunk scan + out[:,0,:]
// ---------------------------------------------------------------------------
__global__ __launch_bounds__(256)
void scan_top_kernel(const float* __restrict__ h0, float* __restrict__ out) {
    const int ch = blockIdx.x * 256 + threadIdx.x;
    const int b = ch >> 9, hh = ch & (HH - 1);

    float x = h0[(size_t)b * HH + hh];
    float h = (x >= 0.f) ? (x + 0.5f) : __fdividef(1.f, 1.f + __expf(-x));
    out[(size_t)b * (TT + 1) * HH + hh] = h;

    #pragma unroll 8
    for (int c = 0; c < NC; c++) {
        g_hin[(size_t)c * NCH + ch] = h;
        h = fmaf(g_cF[(size_t)c * NCH + ch], h, g_cV[(size_t)c * NCH + ch]);
    }
}

// ---------------------------------------------------------------------------
// Kernel 4: apply
// ---------------------------------------------------------------------------
__global__ __launch_bounds__(256)
void scan_apply_kernel(float* __restrict__ out) {
    const int ch = blockIdx.x * 256 + threadIdx.x;
    const int b = ch >> 9, hh = ch & (HH - 1);
    const int chunk = blockIdx.y;
    const int t0 = chunk * CL;
    const size_t gbase = ((size_t)b * TT + t0) * HH + hh;
    const size_t obase = ((size_t)b * (TT + 1) + t0 + 1) * HH + hh;

    float h = g_hin[(size_t)chunk * NCH + ch];
    #pragma unroll 8
    for (int t = 0; t < CL; t++) {
        float2 fv = __half22float2(g_fv[gbase + (size_t)t * HH]);
        h = fmaf(fv.x, h, fv.y);
        out[obase + (size_t)t * HH] = h;
    }
}

// ---------------------------------------------------------------------------
extern "C" void kernel_launch(void* const* d_in, const int* in_sizes, int n_in,
                              void* d_out, int out_size) {
    const float* x  = (const float*)d_in[0];
    const float* h0 = (const float*)d_in[1];
    const float* Wf = (const float*)d_in[2];
    const float* bf = (const float*)d_in[3];
    const float* Wi = (const float*)d_in[4];
    const float* bi = (const float*)d_in[5];
    const float* Wh = (const float*)d_in[6];
    const float* bh = (const float*)d_in[7];
    float* out = (float*)d_out;

    cudaFuncSetAttribute(gemm_mma_kernel,
                         cudaFuncAttributeMaxDynamicSharedMemorySize, GEMM_SMEM);

    cvt_x_kernel<<<(size_t)M_TOTAL * DD / 8 / 256, 256>>>(x);
    {
        dim3 g(DD / 32, HH / 32, 3);
        split_w_kernel<<<g, dim3(32, 8)>>>(Wf, Wi, Wh);
    }
    {
        dim3 g(HH / 64, M_TOTAL / 128);    // (8, 256)
        gemm_mma_kernel<<<g, 512, GEMM_SMEM>>>(bf, bi, bh);
    }
    {
        dim3 g(NCH / 256, NC);             // (8, 128)
        scan_chunk_kernel<<<g, 256>>>();
        scan_top_kernel<<<NCH / 256, 256>>>(h0, out);
        scan_apply_kernel<<<g, 256>>>(out);
    }
}

// round 6
// speedup vs baseline: 4.9404x; 1.1662x over previous
#include <cuda_runtime.h>
#include <cuda_fp16.h>
#include <math.h>
#include <stdint.h>

#define BB 4
#define TT 8192
#define DD 512
#define HH 512
#define M_TOTAL (BB*TT)        // 32768
#define NC 128                 // scan chunks
#define CL (TT/NC)             // 64 steps per chunk
#define NCH (BB*HH)            // 2048 channels

// ---------------- device scratch (allocation-free) ----------------
__device__ __half2 g_fv[(size_t)M_TOTAL*HH];  // packed {f, v}, 64MB
__device__ __half  g_x[(size_t)M_TOTAL*DD];   // fp16 x, 32MB
__device__ __half  g_w[3*DD*HH];              // [g][n][k] transposed, fp16
__device__ float   g_cF[(size_t)NC*NCH];
__device__ float   g_cV[(size_t)NC*NCH];
__device__ float   g_hin[(size_t)NC*NCH];

__device__ __forceinline__ uint32_t smem_u32(const void* p) {
    uint32_t a;
    asm("{ .reg .u64 t; cvta.to.shared.u64 t, %1; cvt.u32.u64 %0, t; }" : "=r"(a) : "l"(p));
    return a;
}

#define LDM_X4(r0,r1,r2,r3,addr) \
    asm volatile("ldmatrix.sync.aligned.m8n8.x4.shared.b16 {%0,%1,%2,%3}, [%4];" \
        : "=r"(r0),"=r"(r1),"=r"(r2),"=r"(r3) : "r"(addr))

#define MMA_FP16(c,a,b) \
    asm volatile("mma.sync.aligned.m16n8k16.row.col.f32.f16.f16.f32 " \
        "{%0,%1,%2,%3},{%4,%5,%6,%7},{%8,%9},{%0,%1,%2,%3};" \
        : "+f"((c)[0]),"+f"((c)[1]),"+f"((c)[2]),"+f"((c)[3]) \
        : "r"((a)[0]),"r"((a)[1]),"r"((a)[2]),"r"((a)[3]),"r"((b)[0]),"r"((b)[1]))

struct alignas(8) h2x2 { __half2 a, b; };

// ---------------------------------------------------------------------------
// Prep 1: convert x to fp16
// ---------------------------------------------------------------------------
__global__ __launch_bounds__(256)
void cvt_x_kernel(const float* __restrict__ x) {
    size_t i = ((size_t)blockIdx.x * 256 + threadIdx.x) * 8;
    float4 v0 = *(const float4*)(x + i);
    float4 v1 = *(const float4*)(x + i + 4);
    h2x2 o0, o1;
    o0.a = __floats2half2_rn(v0.x, v0.y);
    o0.b = __floats2half2_rn(v0.z, v0.w);
    o1.a = __floats2half2_rn(v1.x, v1.y);
    o1.b = __floats2half2_rn(v1.z, v1.w);
    ((h2x2*)(g_x + i))[0] = o0;
    ((h2x2*)(g_x + i))[1] = o1;
}

// ---------------------------------------------------------------------------
// Prep 2: transpose W to fp16, layout [g][n][k]
// ---------------------------------------------------------------------------
__global__ __launch_bounds__(256)
void split_w_kernel(const float* __restrict__ Wf, const float* __restrict__ Wi,
                    const float* __restrict__ Wh) {
    __shared__ float t[32][33];
    const float* W = (blockIdx.z == 0) ? Wf : (blockIdx.z == 1) ? Wi : Wh;
    int k0 = blockIdx.x * 32, n0 = blockIdx.y * 32;
    for (int i = threadIdx.y; i < 32; i += 8)
        t[i][threadIdx.x] = W[(size_t)(k0 + i) * HH + n0 + threadIdx.x];
    __syncthreads();
    for (int i = threadIdx.y; i < 32; i += 8) {
        size_t o = (size_t)blockIdx.z * DD * HH + (size_t)(n0 + i) * DD + k0 + threadIdx.x;
        g_w[o] = __float2half(t[threadIdx.x][i]);
    }
}

// ---------------------------------------------------------------------------
// Gate math: u=1+e^{-f_pre}, w=1+e^{-i_pre}: fg=w/(u+w), ig=u/(u+w)
//            g(x)= x>=0 ? x+0.5 : sigmoid(x);  v = ig*g(h_pre)
// ---------------------------------------------------------------------------
__device__ __forceinline__ void gate_fv(float fpre, float ipre, float hpre,
                                        float& f, float& v) {
    float u = 1.f + __expf(-fpre);
    float w = 1.f + __expf(-ipre);
    float r = __fdividef(1.f, u + w);
    f = w * r;
    float ig = u * r;
    float g = (hpre >= 0.f) ? (hpre + 0.5f)
                            : __fdividef(1.f, 1.f + __expf(-hpre));
    v = ig * g;
}

// ---------------------------------------------------------------------------
// Kernel 1: fused 3-gate fp16 GEMM + gate epilogue.
// CTA: 256 thr, M=128, H=32 (x3 gates), BK=64, 3-stage cp.async, 2 CTAs/SM.
// ---------------------------------------------------------------------------
#define NKT    8                     // 512 / 64
#define STAGES 3
#define PITCH  144                   // 128B data + 16B pad; conflict-free
#define ROWS_ST 224                  // 128 (x) + 96 (W: 3g x 32h)
#define STAGE_BYTES (ROWS_ST*PITCH)  // 32256
#define GEMM_SMEM (STAGES*STAGE_BYTES)  // 96768
#define OFF_B   (128*PITCH)

__global__ __launch_bounds__(256, 2)
void gemm_mma_kernel(const float* __restrict__ bf_, const float* __restrict__ bi_,
                     const float* __restrict__ bh_) {
    extern __shared__ char sm[];
    const uint32_t sb = smem_u32(sm);
    const int tid = threadIdx.x;
    const int m0 = blockIdx.y * 128;
    const int h0 = blockIdx.x * 32;

    const int wid = tid >> 5, lane = tid & 31;
    const int wm = wid & 3, wn = wid >> 2;      // 4m x 2n warps; warp 32m x 16h x 3g
    const int grp = lane >> 3, lrow = lane & 7;

    float acc[3][2][2][4];
    #pragma unroll
    for (int g = 0; g < 3; g++)
        #pragma unroll
        for (int mt = 0; mt < 2; mt++)
            #pragma unroll
            for (int nt = 0; nt < 2; nt++)
                #pragma unroll
                for (int j = 0; j < 4; j++) acc[g][mt][nt][j] = 0.f;

    auto issue = [&](int kt) {
        const uint32_t sst = sb + (kt % STAGES) * STAGE_BYTES;
        const int kin = kt * 64;
        #pragma unroll
        for (int i = tid; i < 1792; i += 256) {
            int r = i >> 3, c = i & 7;
            const __half* src;
            if (r < 128) src = g_x + (size_t)(m0 + r) * 512 + kin;
            else {
                int rr = r - 128;
                src = g_w + (size_t)(rr >> 5) * DD * HH
                          + (size_t)(h0 + (rr & 31)) * 512 + kin;
            }
            asm volatile("cp.async.cg.shared.global [%0], [%1], 16;"
                         :: "r"(sst + r * PITCH + c * 16), "l"(src + c * 8));
        }
        asm volatile("cp.async.commit_group;" ::: "memory");
    };

    issue(0); issue(1);

    #pragma unroll 1
    for (int kt = 0; kt < NKT; kt++) {
        asm volatile("cp.async.wait_group 1;" ::: "memory");
        __syncthreads();
        if (kt + 2 < NKT) issue(kt + 2);

        const uint32_t sst = sb + (kt % STAGES) * STAGE_BYTES;

        #pragma unroll
        for (int kk = 0; kk < 4; kk++) {
            const uint32_t acol = (uint32_t)(kk * 2 + (grp >> 1)) * 16;
            const uint32_t bcol = (uint32_t)(kk * 2 + (grp & 1)) * 16;
            uint32_t a[2][4];
            #pragma unroll
            for (int mt = 0; mt < 2; mt++) {
                uint32_t rrow = (uint32_t)(wm * 32 + mt * 16 + lrow + (grp & 1) * 8) * PITCH;
                LDM_X4(a[mt][0], a[mt][1], a[mt][2], a[mt][3], sst + rrow + acol);
            }
            uint32_t b[3][2][2];
            #pragma unroll
            for (int g = 0; g < 3; g++) {
                uint32_t addr = sst + OFF_B
                    + (uint32_t)(g * 32 + wn * 16 + lrow + (grp >> 1) * 8) * PITCH + bcol;
                uint32_t r0, r1, r2, r3;
                LDM_X4(r0, r1, r2, r3, addr);
                b[g][0][0] = r0; b[g][0][1] = r1;
                b[g][1][0] = r2; b[g][1][1] = r3;
            }
            #pragma unroll
            for (int g = 0; g < 3; g++)
                #pragma unroll
                for (int mt = 0; mt < 2; mt++)
                    #pragma unroll
                    for (int nt = 0; nt < 2; nt++)
                        MMA_FP16(acc[g][mt][nt], a[mt], b[g][nt]);
        }
    }

    // epilogue: gate math, write packed {f,v}
    #pragma unroll
    for (int mt = 0; mt < 2; mt++) {
        #pragma unroll
        for (int nt = 0; nt < 2; nt++) {
            const int m = m0 + wm * 32 + mt * 16 + (lane >> 2);
            const int h = h0 + wn * 16 + nt * 8 + 2 * (lane & 3);
            const float b0f = __ldg(&bf_[h]), b1f = __ldg(&bf_[h + 1]);
            const float b0i = __ldg(&bi_[h]), b1i = __ldg(&bi_[h + 1]);
            const float b0h = __ldg(&bh_[h]), b1h = __ldg(&bh_[h + 1]);
            #pragma unroll
            for (int half_ = 0; half_ < 2; half_++) {      // rows m, m+8
                const int mm = m + half_ * 8;
                float f0, v0, f1, v1;
                gate_fv(acc[0][mt][nt][half_*2+0] + b0f,
                        acc[1][mt][nt][half_*2+0] + b0i,
                        acc[2][mt][nt][half_*2+0] + b0h, f0, v0);
                gate_fv(acc[0][mt][nt][half_*2+1] + b1f,
                        acc[1][mt][nt][half_*2+1] + b1i,
                        acc[2][mt][nt][half_*2+1] + b1h, f1, v1);
                h2x2 pk;
                pk.a = __floats2half2_rn(f0, v0);
                pk.b = __floats2half2_rn(f1, v1);
                *(h2x2*)&g_fv[(size_t)mm * HH + h] = pk;
            }
        }
    }
}

// ---------------------------------------------------------------------------
// Kernel 2: per-chunk affine aggregates (h_out = F*h_in + V)
// ---------------------------------------------------------------------------
__global__ __launch_bounds__(256)
void scan_chunk_kernel() {
    const int ch = blockIdx.x * 256 + threadIdx.x;
    const int b = ch >> 9, hh = ch & (HH - 1);
    const int chunk = blockIdx.y;
    const size_t base = ((size_t)b * TT + (size_t)chunk * CL) * HH + hh;

    float F = 1.f, V = 0.f;
    #pragma unroll 8
    for (int t = 0; t < CL; t++) {
        float2 fv = __half22float2(g_fv[base + (size_t)t * HH]);
        V = fmaf(fv.x, V, fv.y);
        F = F * fv.x;
    }
    g_cF[(size_t)chunk * NCH + ch] = F;
    g_cV[(size_t)chunk * NCH + ch] = V;
}

// ---------------------------------------------------------------------------
// Kernel 3: serial cross-chunk scan + out[:,0,:]
// ---------------------------------------------------------------------------
__global__ __launch_bounds__(256)
void scan_top_kernel(const float* __restrict__ h0, float* __restrict__ out) {
    const int ch = blockIdx.x * 256 + threadIdx.x;
    const int b = ch >> 9, hh = ch & (HH - 1);

    float x = h0[(size_t)b * HH + hh];
    float h = (x >= 0.f) ? (x + 0.5f) : __fdividef(1.f, 1.f + __expf(-x));
    out[(size_t)b * (TT + 1) * HH + hh] = h;

    #pragma unroll 8
    for (int c = 0; c < NC; c++) {
        g_hin[(size_t)c * NCH + ch] = h;
        h = fmaf(g_cF[(size_t)c * NCH + ch], h, g_cV[(size_t)c * NCH + ch]);
    }
}

// ---------------------------------------------------------------------------
// Kernel 4: apply
// ---------------------------------------------------------------------------
__global__ __launch_bounds__(256)
void scan_apply_kernel(float* __restrict__ out) {
    const int ch = blockIdx.x * 256 + threadIdx.x;
    const int b = ch >> 9, hh = ch & (HH - 1);
    const int chunk = blockIdx.y;
    const int t0 = chunk * CL;
    const size_t gbase = ((size_t)b * TT + t0) * HH + hh;
    const size_t obase = ((size_t)b * (TT + 1) + t0 + 1) * HH + hh;

    float h = g_hin[(size_t)chunk * NCH + ch];
    #pragma unroll 8
    for (int t = 0; t < CL; t++) {
        float2 fv = __half22float2(g_fv[gbase + (size_t)t * HH]);
        h = fmaf(fv.x, h, fv.y);
        out[obase + (size_t)t * HH] = h;
    }
}

// ---------------------------------------------------------------------------
extern "C" void kernel_launch(void* const* d_in, const int* in_sizes, int n_in,
                              void* d_out, int out_size) {
    const float* x  = (const float*)d_in[0];
    const float* h0 = (const float*)d_in[1];
    const float* Wf = (const float*)d_in[2];
    const float* bf = (const float*)d_in[3];
    const float* Wi = (const float*)d_in[4];
    const float* bi = (const float*)d_in[5];
    const float* Wh = (const float*)d_in[6];
    const float* bh = (const float*)d_in[7];
    float* out = (float*)d_out;

    cudaFuncSetAttribute(gemm_mma_kernel,
                         cudaFuncAttributeMaxDynamicSharedMemorySize, GEMM_SMEM);

    cvt_x_kernel<<<(size_t)M_TOTAL * DD / 8 / 256, 256>>>(x);
    {
        dim3 g(DD / 32, HH / 32, 3);
        split_w_kernel<<<g, dim3(32, 8)>>>(Wf, Wi, Wh);
    }
    {
        dim3 g(HH / 32, M_TOTAL / 128);    // (16, 256)
        gemm_mma_kernel<<<g, 256, GEMM_SMEM>>>(bf, bi, bh);
    }
    {
        dim3 g(NCH / 256, NC);             // (8, 128)
        scan_chunk_kernel<<<g, 256>>>();
        scan_top_kernel<<<NCH / 256, 256>>>(h0, out);
        scan_apply_kernel<<<g, 256>>>(out);
    }
}